// round 14
// baseline (speedup 1.0000x reference)
#include <cuda_runtime.h>
#include <stdint.h>
#include <math.h>

#define NMAX   2048
#define NW     64          // bitset words per row
#define K      128         // MAX_EGO
#define FNUM   16
#define M      8
#define LAB    16
#define LEVELS 4

// ---------------- device scratch ----------------
// g_abits/g_mask start zeroed (module load); edge scatter is idempotent OR of
// the same edge set every launch -> safe across graph replays without zeroing.
__device__ __align__(16) uint32_t g_abits[NMAX * NW];
__device__ unsigned long long g_mask[NMAX];            // word-occupancy mask per row
__device__ __align__(16) uint32_t g_hf[LEVELS * K];   // [t][f*8+m]
__device__ uint8_t  g_flab[K];                         // filter slot level-0 label
__device__ uint32_t g_fmb[4];                          // slot validity bits
__device__ float    g_selff[FNUM];

__device__ __forceinline__ uint32_t mixh(uint32_t h) {
    h ^= h >> 16; h *= 0x7FEB352Du;
    h ^= h >> 15; h *= 0x846CA68Bu;
    h ^= h >> 16;
    return h;
}

// ---------------- K1: edge scatter + filter precompute (fused) ----------------
__global__ void k_build(const int* __restrict__ ei, int E2,
                        const float* __restrict__ A, const float* __restrict__ X) {
    const int tid = threadIdx.x;
    if (blockIdx.x < gridDim.x - 1) {
        int e = blockIdx.x * blockDim.x + tid;
        if (e < E2) {
            int s = ei[e];
            int d = ei[E2 + e];
            atomicOr(&g_abits[s * NW + (d >> 5)], 1u << (d & 31));
            atomicOr(&g_abits[d * NW + (s >> 5)], 1u << (s & 31));
            atomicOr(&g_mask[s], 1ull << (d >> 5));
            atomicOr(&g_mask[d], 1ull << (s >> 5));
        }
        return;
    }

    // ---- last block: filter graphs (fully unrolled, register-resident) ----
    __shared__ uint32_t adjS[FNUM * M];
    __shared__ uint32_t h0S[FNUM * M];
    if (tid < FNUM * M) {
        const int f = tid >> 3, m = tid & 7;
        uint32_t r = 0;
        const float* ar = A + (f * M + m) * M;
        #pragma unroll
        for (int j = 0; j < M; j++) if (ar[j] > 0.f) r |= 1u << j;
        adjS[tid] = r;
        const float4* xr = (const float4*)(X + (f * M + m) * LAB);
        float4 a0 = xr[0], a1 = xr[1], a2 = xr[2], a3 = xr[3];
        int lab = 0; float bv = a0.x;
        #define CK(v, i) if ((v) > bv) { bv = (v); lab = (i); }
        CK(a0.y, 1)  CK(a0.z, 2)  CK(a0.w, 3)
        CK(a1.x, 4)  CK(a1.y, 5)  CK(a1.z, 6)  CK(a1.w, 7)
        CK(a2.x, 8)  CK(a2.y, 9)  CK(a2.z, 10) CK(a2.w, 11)
        CK(a3.x, 12) CK(a3.y, 13) CK(a3.z, 14) CK(a3.w, 15)
        #undef CK
        h0S[tid] = mixh((uint32_t)lab + 1u);
        g_flab[tid] = (uint8_t)lab;
    }
    __syncthreads();
    if (tid >= FNUM) return;
    const int f = tid;

    uint32_t adj[M], h[M];
    #pragma unroll
    for (int m = 0; m < M; m++) { adj[m] = adjS[f * M + m]; h[m] = h0S[f * M + m]; }

    int lbl[M];
    #pragma unroll
    for (int m = 0; m < M; m++) lbl[m] = m;
    #pragma unroll
    for (int it = 0; it < M; it++) {
        int nl[M];
        #pragma unroll
        for (int m = 0; m < M; m++) {
            int mn = lbl[m];
            const uint32_t r = adj[m];
            #pragma unroll
            for (int j = 0; j < M; j++)
                if ((r >> j) & 1u) mn = min(mn, lbl[j]);
            nl[m] = mn;
        }
        #pragma unroll
        for (int m = 0; m < M; m++) lbl[m] = nl[m];
    }
    int cntc[M];
    #pragma unroll
    for (int m = 0; m < M; m++) {
        int c = 0;
        #pragma unroll
        for (int j = 0; j < M; j++) c += (lbl[j] == lbl[m]);
        cntc[m] = c;
    }
    int best = 0;
    #pragma unroll
    for (int m = 1; m < M; m++) if (cntc[m] > cntc[best]) best = m;   // first max
    int lbest = lbl[0];
    #pragma unroll
    for (int m = 1; m < M; m++) if (m == best) lbest = lbl[m];
    uint32_t maskbits = 0;
    #pragma unroll
    for (int m = 0; m < M; m++) if (lbl[m] == lbest) maskbits |= 1u << m;

    uint32_t adjm[M];
    #pragma unroll
    for (int m = 0; m < M; m++)
        adjm[m] = ((maskbits >> m) & 1u) ? (adj[m] & maskbits) : 0u;

    int selff = 0;
    #pragma unroll
    for (int t = 0; t < LEVELS; t++) {
        if (t > 0) {
            uint32_t mh[M], nh[M];
            #pragma unroll
            for (int m = 0; m < M; m++) mh[m] = mixh(h[m]);
            #pragma unroll
            for (int m = 0; m < M; m++) {
                uint32_t msg = 0;
                const uint32_t r = adjm[m];
                #pragma unroll
                for (int j = 0; j < M; j++)
                    if ((r >> j) & 1u) msg += mh[j];
                nh[m] = mixh(h[m] * 0x9E3779B1u + msg);
            }
            #pragma unroll
            for (int m = 0; m < M; m++) h[m] = nh[m];
        }
        #pragma unroll
        for (int m = 0; m < M; m++) g_hf[t * K + f * M + m] = h[m];
        #pragma unroll
        for (int m = 0; m < M; m++)
            if ((maskbits >> m) & 1u) {
                #pragma unroll
                for (int j = 0; j < M; j++)
                    if (((maskbits >> j) & 1u) && h[m] == h[j]) selff++;
            }
    }
    g_selff[f] = (float)selff;
    ((uint8_t*)g_fmb)[f] = (uint8_t)maskbits;
}

// ---------------- K2: main per-seed kernel ----------------
__global__ void __launch_bounds__(128, 16) k_main(const float* __restrict__ x,
                                                  float* __restrict__ out) {
    const int u    = blockIdx.x;
    const int tid  = threadIdx.x;
    const int lane = tid & 31;

    __shared__ __align__(16) uint32_t cur[NW];
    __shared__ __align__(16) uint32_t prev[NW];
    __shared__ __align__(16) uint32_t sel[NW];
    __shared__ uint16_t flist[NMAX];
    __shared__ uint8_t  map8[NMAX];
    __shared__ int16_t  members[K];
    __shared__ __align__(16) uint32_t sh2[2][K];     // double-buffered hash publish
    __shared__ uint32_t smh2[2][K];                  // double-buffered mixed hashes
    __shared__ __align__(16) uint32_t s_hf[LEVELS * K];
    __shared__ uint32_t pres3[3][32];                // per-level presence blooms
    __shared__ uint32_t dup3[3][32];                 // per-level duplicate blooms
    __shared__ int      s_hist[LAB];                 // level-0 label histogram
    __shared__ float    s_selff[FNUM];
    __shared__ int      s_cross[FNUM];
    __shared__ int      s_selfe, s_fcnt, s_cnt, s_wsum;

    // hop 1 done directly: cur = row(u) | {u};  prev = {u}
    if (tid < NW) {
        const uint32_t seedbit = (tid == (u >> 5)) ? (1u << (u & 31)) : 0u;
        cur[tid]  = g_abits[u * NW + tid] | seedbit;
        prev[tid] = seedbit;
        sel[tid]  = 0u;
    }
    #pragma unroll
    for (int t = 0; t < LEVELS; t++) s_hf[t * K + tid] = g_hf[t * K + tid];
    const uint32_t fmbit = (g_fmb[tid >> 5] >> (tid & 31)) & 1u;  // my slot's validity
    const uint32_t flab  = g_flab[tid];                            // my slot's level-0 label
    if (tid < 96) { pres3[tid >> 5][tid & 31] = 0u; dup3[tid >> 5][tid & 31] = 0u; }
    if (tid < LAB) s_hist[tid] = 0;
    if (tid < FNUM) { s_selff[tid] = g_selff[tid]; s_cross[tid] = 0; }
    if (tid == 0)   s_selfe = 0;
    __syncthreads();

    // ---- hops 2,3: frontier list + mask-guided sparse row OR ----
    for (int hop = 1; hop < 3; hop++) {
        uint32_t fw = 0;
        if (tid < NW) { fw = cur[tid] & ~prev[tid]; prev[tid] = cur[tid]; }
        if (tid == 0) s_fcnt = 0;
        __syncthreads();
        while (fw) {
            int b = __ffs(fw) - 1; fw &= fw - 1;
            int p = atomicAdd(&s_fcnt, 1);
            flist[p] = (uint16_t)((tid << 5) + b);
        }
        __syncthreads();
        const int V = s_fcnt;
        const int k8 = tid & 7;                         // my byte of the word-mask
        for (int i = tid >> 3; i < V; i += 16) {        // 8 threads per frontier vertex
            const int v = (int)flist[i];
            uint32_t slice = (uint32_t)(g_mask[v] >> (k8 * 8)) & 0xFFu;
            while (slice) {
                int b = __ffs(slice) - 1; slice &= slice - 1;
                const int w = k8 * 8 + b;
                atomicOr(&cur[w], g_abits[v * NW + w]);
            }
        }
        __syncthreads();
    }

    // ---- enumerate members: seed first, ascending, cap K ----
    if (tid < NW) {
        uint32_t wv = cur[tid];
        if (tid == (u >> 5)) wv &= ~(1u << (u & 31));
        prev[tid] = wv;                       // seedless bits
    }
    __syncthreads();
    int c  = (tid < NW) ? __popc(prev[tid]) : 0;
    int cs = c;
    #pragma unroll
    for (int off = 1; off < 32; off <<= 1) {
        int n = __shfl_up_sync(0xffffffffu, cs, off);
        if (lane >= off) cs += n;
    }
    if (tid == 31) s_wsum = cs;
    __syncthreads();
    if (tid >= 32 && tid < 64) cs += s_wsum;
    if (tid == 63) s_cnt = min(cs + 1, K);
    if (tid < NW) {
        uint32_t wv = prev[tid];
        int base = 1 + (cs - c);
        while (wv && base < K) { int b = __ffs(wv) - 1; wv &= wv - 1; members[base++] = (int16_t)((tid << 5) + b); }
    }
    if (tid == 0) members[0] = (int16_t)u;
    __syncthreads();
    const int  cnt   = s_cnt;
    const bool valid = tid < cnt;
    const uint32_t pad = (uint32_t)(K - cnt);   // zero-padding count in sh buffers

    // ---- selected bitset + global->local map ----
    const int g = valid ? (int)members[tid] : 0;
    if (valid) {
        map8[g] = (uint8_t)tid;
        atomicOr(&sel[g >> 5], 1u << (g & 31));
    }
    __syncthreads();

    // ---- local adjacency (128-bit): mask-guided sparse intersection ----
    uint64_t rlo = 0ull, rhi = 0ull;
    uint32_t hreg = 0u;
    int mylab = 0;
    if (valid) {
        uint64_t m = g_mask[g];
        const uint32_t* arow = &g_abits[g * NW];
        while (m) {
            const int w = __ffsll((long long)m) - 1; m &= m - 1;
            uint32_t bits = arow[w] & sel[w];
            const int base = w * 32;
            while (bits) {
                int b = __ffs(bits) - 1; bits &= bits - 1;
                int j = map8[base + b];
                if (j < 64) rlo |= 1ull << j; else rhi |= 1ull << (j - 64);
            }
        }
        const float4* xr = (const float4*)(x + g * LAB);
        float4 a0 = xr[0], a1 = xr[1], a2 = xr[2], a3 = xr[3];
        int lab = 0; float bv = a0.x;
        #define CK(v, i) if ((v) > bv) { bv = (v); lab = (i); }
        CK(a0.y, 1)  CK(a0.z, 2)  CK(a0.w, 3)
        CK(a1.x, 4)  CK(a1.y, 5)  CK(a1.z, 6)  CK(a1.w, 7)
        CK(a2.x, 8)  CK(a2.y, 9)  CK(a2.z, 10) CK(a2.w, 11)
        CK(a3.x, 12) CK(a3.y, 13) CK(a3.z, 14) CK(a3.w, 15)
        #undef CK
        mylab = lab;
        hreg = mixh((uint32_t)lab + 1u);
    }

    uint32_t se_acc = 0u;
    uint32_t cr_acc = 0u;

    // ======== level 0: histogram (mixh bijective -> hash eq == label eq) ========
    {
        smh2[0][tid] = mixh(hreg);
        if (valid) atomicAdd(&s_hist[mylab], 1);
        __syncthreads();

        if (valid) se_acc += (uint32_t)s_hist[mylab];
        if (fmbit)  cr_acc += (uint32_t)s_hist[flab];

        if (valid) {
            uint32_t msg = 0;
            uint64_t r = rlo;
            while (r) { int b = __ffsll((long long)r) - 1; r &= r - 1; msg += smh2[0][b]; }
            r = rhi;
            while (r) { int b = __ffsll((long long)r) - 1; r &= r - 1; msg += smh2[0][64 + b]; }
            hreg = mixh(hreg * 0x9E3779B1u + msg);
        }
        // no barrier: level-1 publish touches sh2[1]/smh2[1]/pres3[0] only
    }

    // ======== levels 1..3: one barrier per level ========
    #pragma unroll 1
    for (int t = 1; t < LEVELS; t++) {
        const int p = t & 1;
        const int q = t - 1;                   // this level's bloom buffer
        sh2[p][tid] = valid ? hreg : 0u;
        if (t < LEVELS - 1) smh2[p][tid] = mixh(hreg);
        if (valid) {
            const uint32_t bit = 1u << (hreg & 31);
            uint32_t old = atomicOr(&pres3[q][(hreg >> 5) & 31], bit);
            if (old & bit) atomicOr(&dup3[q][(hreg >> 5) & 31], bit);
        }
        __syncthreads();

        // each lane holds 4 member hashes: lane j covers sh[4j..4j+3]
        const uint4 vme = ((const uint4*)sh2[p])[lane];

        // ---- self: exact count for duplicate-flagged lanes only ----
        {
            const bool dupme = valid &&
                ((dup3[q][(hreg >> 5) & 31] >> (hreg & 31)) & 1u);
            if (valid && !dupme) se_acc += 1u;       // unique hash matches only itself
            uint32_t need = __ballot_sync(0xffffffffu, dupme);
            while (need) {
                const int l = __ffs(need) - 1; need &= need - 1;
                const uint32_t key = __shfl_sync(0xffffffffu, hreg, l);
                uint32_t cc = (vme.x == key) + (vme.y == key) + (vme.z == key) + (vme.w == key);
                cc = __reduce_add_sync(0xffffffffu, cc);
                if (lane == l) se_acc += (key == 0u) ? cc - pad : cc;
            }
        }
        // ---- cross: exact count for presence-gated filter slots ----
        {
            const uint32_t hk = s_hf[t * K + tid];
            const bool hit = fmbit &&
                ((pres3[q][(hk >> 5) & 31] >> (hk & 31)) & 1u);
            uint32_t need = __ballot_sync(0xffffffffu, hit);
            while (need) {
                const int l = __ffs(need) - 1; need &= need - 1;
                const uint32_t key = __shfl_sync(0xffffffffu, hk, l);
                uint32_t cc = (vme.x == key) + (vme.y == key) + (vme.z == key) + (vme.w == key);
                cc = __reduce_add_sync(0xffffffffu, cc);
                if (lane == l) cr_acc += (key == 0u) ? cc - pad : cc;
            }
        }

        if (t < LEVELS - 1 && valid) {
            uint32_t msg = 0;
            uint64_t r = rlo;
            while (r) { int b = __ffsll((long long)r) - 1; r &= r - 1; msg += smh2[p][b]; }
            r = rhi;
            while (r) { int b = __ffsll((long long)r) - 1; r &= r - 1; msg += smh2[p][64 + b]; }
            hreg = mixh(hreg * 0x9E3779B1u + msg);
        }
        // no trailing barrier: next publish writes the other buffers
    }

    // ---- final reductions ----
    unsigned se = __reduce_add_sync(0xffffffffu, se_acc);
    if (lane == 0 && se) atomicAdd(&s_selfe, (int)se);

    uint32_t cr = cr_acc;                      // already gated by fmbit
    cr += __shfl_down_sync(0xffffffffu, cr, 4, 8);
    cr += __shfl_down_sync(0xffffffffu, cr, 2, 8);
    cr += __shfl_down_sync(0xffffffffu, cr, 1, 8);
    if ((lane & 7) == 0) atomicAdd(&s_cross[tid >> 3], (int)cr);
    __syncthreads();

    if (tid < FNUM) {
        float denom = sqrtf((float)s_selfe * s_selff[tid]);
        float v = (float)s_cross[tid] / denom;
        if (!isfinite(v)) v = 0.f;
        out[u * FNUM + tid] = v;
    }
}

// ---------------- launch ----------------
extern "C" void kernel_launch(void* const* d_in, const int* in_sizes, int n_in,
                              void* d_out, int out_size) {
    const float* x  = (const float*)d_in[0];
    const int*   ei = (const int*)d_in[1];
    const float* A  = (const float*)d_in[3];
    const float* X  = (const float*)d_in[4];
    float* out = (float*)d_out;

    const int N  = in_sizes[0] / LAB;
    const int E2 = in_sizes[1] / 2;

    const int eblocks = (E2 + 255) / 256;
    k_build<<<eblocks + 1, 256>>>(ei, E2, A, X);
    k_main<<<N, 128>>>(x, out);
}

// round 15
// speedup vs baseline: 1.0626x; 1.0626x over previous
#include <cuda_runtime.h>
#include <stdint.h>
#include <math.h>

#define NMAX   2048
#define NW     64          // bitset words per row
#define K      128         // MAX_EGO
#define FNUM   16
#define M      8
#define LAB    16
#define LEVELS 4

// ---------------- device scratch ----------------
// g_abits/g_mask start zeroed (module load); edge scatter is idempotent OR of
// the same edge set every launch -> safe across graph replays without zeroing.
__device__ __align__(16) uint32_t g_abits[NMAX * NW];
__device__ unsigned long long g_mask[NMAX];            // word-occupancy mask per row
__device__ __align__(16) uint32_t g_hf[LEVELS * K];   // [t][f*8+m]
__device__ uint8_t  g_flab[K];                         // filter slot level-0 label
__device__ uint32_t g_fmb[4];                          // slot validity bits
__device__ float    g_selff[FNUM];

__device__ __forceinline__ uint32_t mixh(uint32_t h) {
    h ^= h >> 16; h *= 0x7FEB352Du;
    h ^= h >> 15; h *= 0x846CA68Bu;
    h ^= h >> 16;
    return h;
}

// ---------------- K1: edge scatter + filter precompute (fused) ----------------
__global__ void k_build(const int* __restrict__ ei, int E2,
                        const float* __restrict__ A, const float* __restrict__ X) {
    const int tid = threadIdx.x;
    if (blockIdx.x < gridDim.x - 1) {
        int e = blockIdx.x * blockDim.x + tid;
        if (e < E2) {
            int s = ei[e];
            int d = ei[E2 + e];
            atomicOr(&g_abits[s * NW + (d >> 5)], 1u << (d & 31));
            atomicOr(&g_abits[d * NW + (s >> 5)], 1u << (s & 31));
            atomicOr(&g_mask[s], 1ull << (d >> 5));
            atomicOr(&g_mask[d], 1ull << (s >> 5));
        }
        return;
    }

    // ---- last block: filter graphs (fully unrolled, register-resident) ----
    __shared__ uint32_t adjS[FNUM * M];
    __shared__ uint32_t h0S[FNUM * M];
    if (tid < FNUM * M) {
        const int f = tid >> 3, m = tid & 7;
        uint32_t r = 0;
        const float* ar = A + (f * M + m) * M;
        #pragma unroll
        for (int j = 0; j < M; j++) if (ar[j] > 0.f) r |= 1u << j;
        adjS[tid] = r;
        const float4* xr = (const float4*)(X + (f * M + m) * LAB);
        float4 a0 = xr[0], a1 = xr[1], a2 = xr[2], a3 = xr[3];
        int lab = 0; float bv = a0.x;
        #define CK(v, i) if ((v) > bv) { bv = (v); lab = (i); }
        CK(a0.y, 1)  CK(a0.z, 2)  CK(a0.w, 3)
        CK(a1.x, 4)  CK(a1.y, 5)  CK(a1.z, 6)  CK(a1.w, 7)
        CK(a2.x, 8)  CK(a2.y, 9)  CK(a2.z, 10) CK(a2.w, 11)
        CK(a3.x, 12) CK(a3.y, 13) CK(a3.z, 14) CK(a3.w, 15)
        #undef CK
        h0S[tid] = mixh((uint32_t)lab + 1u);
        g_flab[tid] = (uint8_t)lab;
    }
    __syncthreads();
    if (tid >= FNUM) return;
    const int f = tid;

    uint32_t adj[M], h[M];
    #pragma unroll
    for (int m = 0; m < M; m++) { adj[m] = adjS[f * M + m]; h[m] = h0S[f * M + m]; }

    int lbl[M];
    #pragma unroll
    for (int m = 0; m < M; m++) lbl[m] = m;
    #pragma unroll
    for (int it = 0; it < M; it++) {
        int nl[M];
        #pragma unroll
        for (int m = 0; m < M; m++) {
            int mn = lbl[m];
            const uint32_t r = adj[m];
            #pragma unroll
            for (int j = 0; j < M; j++)
                if ((r >> j) & 1u) mn = min(mn, lbl[j]);
            nl[m] = mn;
        }
        #pragma unroll
        for (int m = 0; m < M; m++) lbl[m] = nl[m];
    }
    int cntc[M];
    #pragma unroll
    for (int m = 0; m < M; m++) {
        int c = 0;
        #pragma unroll
        for (int j = 0; j < M; j++) c += (lbl[j] == lbl[m]);
        cntc[m] = c;
    }
    int best = 0;
    #pragma unroll
    for (int m = 1; m < M; m++) if (cntc[m] > cntc[best]) best = m;   // first max
    int lbest = lbl[0];
    #pragma unroll
    for (int m = 1; m < M; m++) if (m == best) lbest = lbl[m];
    uint32_t maskbits = 0;
    #pragma unroll
    for (int m = 0; m < M; m++) if (lbl[m] == lbest) maskbits |= 1u << m;

    uint32_t adjm[M];
    #pragma unroll
    for (int m = 0; m < M; m++)
        adjm[m] = ((maskbits >> m) & 1u) ? (adj[m] & maskbits) : 0u;

    int selff = 0;
    #pragma unroll
    for (int t = 0; t < LEVELS; t++) {
        if (t > 0) {
            uint32_t mh[M], nh[M];
            #pragma unroll
            for (int m = 0; m < M; m++) mh[m] = mixh(h[m]);
            #pragma unroll
            for (int m = 0; m < M; m++) {
                uint32_t msg = 0;
                const uint32_t r = adjm[m];
                #pragma unroll
                for (int j = 0; j < M; j++)
                    if ((r >> j) & 1u) msg += mh[j];
                nh[m] = mixh(h[m] * 0x9E3779B1u + msg);
            }
            #pragma unroll
            for (int m = 0; m < M; m++) h[m] = nh[m];
        }
        #pragma unroll
        for (int m = 0; m < M; m++) g_hf[t * K + f * M + m] = h[m];
        #pragma unroll
        for (int m = 0; m < M; m++)
            if ((maskbits >> m) & 1u) {
                #pragma unroll
                for (int j = 0; j < M; j++)
                    if (((maskbits >> j) & 1u) && h[m] == h[j]) selff++;
            }
    }
    g_selff[f] = (float)selff;
    ((uint8_t*)g_fmb)[f] = (uint8_t)maskbits;
}

// ---------------- K2: main per-seed kernel ----------------
__global__ void __launch_bounds__(128, 16) k_main(const float* __restrict__ x,
                                                  float* __restrict__ out) {
    const int u    = blockIdx.x;
    const int tid  = threadIdx.x;
    const int lane = tid & 31;

    __shared__ __align__(16) uint32_t cur[NW];
    __shared__ __align__(16) uint32_t prev[NW];
    __shared__ __align__(16) uint32_t sel[NW];
    // 4KB scratch: flist (BFS phase) aliases map8 (post-BFS phase) -- disjoint lifetimes
    __shared__ __align__(16) uint8_t scratch[NMAX * 2];
    uint16_t* const flist = (uint16_t*)scratch;      // [NMAX] during BFS hops
    uint8_t*  const map8  = scratch;                  // [NMAX] after enumeration
    __shared__ int16_t  members[K];
    __shared__ __align__(16) uint32_t sh2[2][K];     // double-buffered hash publish
    __shared__ uint32_t smh2[2][K];                  // double-buffered mixed hashes
    __shared__ uint32_t pres3[3][32];                // per-level presence blooms
    __shared__ uint32_t dup3[3][32];                 // per-level duplicate blooms
    __shared__ int      s_hist[LAB];                 // level-0 label histogram
    __shared__ float    s_selff[FNUM];
    __shared__ int      s_cross[FNUM];
    __shared__ int      s_selfe, s_fcnt, s_cnt, s_wsum;

    // hop 1 done directly: cur = row(u) | {u};  prev = {u}
    if (tid < NW) {
        const uint32_t seedbit = (tid == (u >> 5)) ? (1u << (u & 31)) : 0u;
        cur[tid]  = g_abits[u * NW + tid] | seedbit;
        prev[tid] = seedbit;
        sel[tid]  = 0u;
    }
    const uint32_t fmbit = (g_fmb[tid >> 5] >> (tid & 31)) & 1u;  // my slot's validity
    const uint32_t flab  = g_flab[tid];                            // my slot's level-0 label
    if (tid < 96) { pres3[tid >> 5][tid & 31] = 0u; dup3[tid >> 5][tid & 31] = 0u; }
    if (tid < LAB) s_hist[tid] = 0;
    if (tid < FNUM) { s_selff[tid] = g_selff[tid]; s_cross[tid] = 0; }
    if (tid == 0)   s_selfe = 0;
    __syncthreads();

    // ---- hops 2,3: frontier list + mask-guided sparse row OR ----
    for (int hop = 1; hop < 3; hop++) {
        uint32_t fw = 0;
        if (tid < NW) { fw = cur[tid] & ~prev[tid]; prev[tid] = cur[tid]; }
        if (tid == 0) s_fcnt = 0;
        __syncthreads();
        while (fw) {
            int b = __ffs(fw) - 1; fw &= fw - 1;
            int p = atomicAdd(&s_fcnt, 1);
            flist[p] = (uint16_t)((tid << 5) + b);
        }
        __syncthreads();
        const int V = s_fcnt;
        const int k8 = tid & 7;                         // my byte of the word-mask
        for (int i = tid >> 3; i < V; i += 16) {        // 8 threads per frontier vertex
            const int v = (int)flist[i];
            uint32_t slice = (uint32_t)(g_mask[v] >> (k8 * 8)) & 0xFFu;
            while (slice) {
                int b = __ffs(slice) - 1; slice &= slice - 1;
                const int w = k8 * 8 + b;
                atomicOr(&cur[w], g_abits[v * NW + w]);
            }
        }
        __syncthreads();
    }

    // ---- enumerate members: seed first, ascending, cap K ----
    if (tid < NW) {
        uint32_t wv = cur[tid];
        if (tid == (u >> 5)) wv &= ~(1u << (u & 31));
        prev[tid] = wv;                       // seedless bits
    }
    __syncthreads();
    int c  = (tid < NW) ? __popc(prev[tid]) : 0;
    int cs = c;
    #pragma unroll
    for (int off = 1; off < 32; off <<= 1) {
        int n = __shfl_up_sync(0xffffffffu, cs, off);
        if (lane >= off) cs += n;
    }
    if (tid == 31) s_wsum = cs;
    __syncthreads();
    if (tid >= 32 && tid < 64) cs += s_wsum;
    if (tid == 63) s_cnt = min(cs + 1, K);
    if (tid < NW) {
        uint32_t wv = prev[tid];
        int base = 1 + (cs - c);
        while (wv && base < K) { int b = __ffs(wv) - 1; wv &= wv - 1; members[base++] = (int16_t)((tid << 5) + b); }
    }
    if (tid == 0) members[0] = (int16_t)u;
    __syncthreads();
    const int  cnt   = s_cnt;
    const bool valid = tid < cnt;
    const uint32_t pad = (uint32_t)(K - cnt);   // zero-padding count in sh buffers

    // ---- selected bitset + global->local map (map8 aliases flist; BFS done) ----
    const int g = valid ? (int)members[tid] : 0;
    if (valid) {
        map8[g] = (uint8_t)tid;
        atomicOr(&sel[g >> 5], 1u << (g & 31));
    }
    __syncthreads();

    // ---- local adjacency (128-bit): mask-guided sparse intersection ----
    uint64_t rlo = 0ull, rhi = 0ull;
    uint32_t hreg = 0u;
    int mylab = 0;
    if (valid) {
        uint64_t m = g_mask[g];
        const uint32_t* arow = &g_abits[g * NW];
        while (m) {
            const int w = __ffsll((long long)m) - 1; m &= m - 1;
            uint32_t bits = arow[w] & sel[w];
            const int base = w * 32;
            while (bits) {
                int b = __ffs(bits) - 1; bits &= bits - 1;
                int j = map8[base + b];
                if (j < 64) rlo |= 1ull << j; else rhi |= 1ull << (j - 64);
            }
        }
        const float4* xr = (const float4*)(x + g * LAB);
        float4 a0 = xr[0], a1 = xr[1], a2 = xr[2], a3 = xr[3];
        int lab = 0; float bv = a0.x;
        #define CK(v, i) if ((v) > bv) { bv = (v); lab = (i); }
        CK(a0.y, 1)  CK(a0.z, 2)  CK(a0.w, 3)
        CK(a1.x, 4)  CK(a1.y, 5)  CK(a1.z, 6)  CK(a1.w, 7)
        CK(a2.x, 8)  CK(a2.y, 9)  CK(a2.z, 10) CK(a2.w, 11)
        CK(a3.x, 12) CK(a3.y, 13) CK(a3.z, 14) CK(a3.w, 15)
        #undef CK
        mylab = lab;
        hreg = mixh((uint32_t)lab + 1u);
    }

    uint32_t se_acc = 0u;
    uint32_t cr_acc = 0u;

    // ======== level 0: histogram (mixh bijective -> hash eq == label eq) ========
    {
        smh2[0][tid] = mixh(hreg);
        if (valid) atomicAdd(&s_hist[mylab], 1);
        __syncthreads();

        if (valid) se_acc += (uint32_t)s_hist[mylab];
        if (fmbit)  cr_acc += (uint32_t)s_hist[flab];

        if (valid) {
            uint32_t msg = 0;
            uint64_t r = rlo;
            while (r) { int b = __ffsll((long long)r) - 1; r &= r - 1; msg += smh2[0][b]; }
            r = rhi;
            while (r) { int b = __ffsll((long long)r) - 1; r &= r - 1; msg += smh2[0][64 + b]; }
            hreg = mixh(hreg * 0x9E3779B1u + msg);
        }
        // no barrier: level-1 publish touches sh2[1]/smh2[1]/pres3[0] only
    }

    // ======== levels 1..3: one barrier per level ========
    #pragma unroll 1
    for (int t = 1; t < LEVELS; t++) {
        const int p = t & 1;
        const int q = t - 1;                   // this level's bloom buffer
        sh2[p][tid] = valid ? hreg : 0u;
        if (t < LEVELS - 1) smh2[p][tid] = mixh(hreg);
        if (valid) {
            const uint32_t bit = 1u << (hreg & 31);
            uint32_t old = atomicOr(&pres3[q][(hreg >> 5) & 31], bit);
            if (old & bit) atomicOr(&dup3[q][(hreg >> 5) & 31], bit);
        }
        const uint32_t hk = g_hf[t * K + tid];  // cross key straight from global (L2)
        __syncthreads();

        // each lane holds 4 member hashes: lane j covers sh[4j..4j+3]
        const uint4 vme = ((const uint4*)sh2[p])[lane];

        // ---- self: exact count for duplicate-flagged lanes only ----
        {
            const bool dupme = valid &&
                ((dup3[q][(hreg >> 5) & 31] >> (hreg & 31)) & 1u);
            if (valid && !dupme) se_acc += 1u;       // unique hash matches only itself
            uint32_t need = __ballot_sync(0xffffffffu, dupme);
            while (need) {
                const int l = __ffs(need) - 1; need &= need - 1;
                const uint32_t key = __shfl_sync(0xffffffffu, hreg, l);
                uint32_t cc = (vme.x == key) + (vme.y == key) + (vme.z == key) + (vme.w == key);
                cc = __reduce_add_sync(0xffffffffu, cc);
                if (lane == l) se_acc += (key == 0u) ? cc - pad : cc;
            }
        }
        // ---- cross: exact count for presence-gated filter slots ----
        {
            const bool hit = fmbit &&
                ((pres3[q][(hk >> 5) & 31] >> (hk & 31)) & 1u);
            uint32_t need = __ballot_sync(0xffffffffu, hit);
            while (need) {
                const int l = __ffs(need) - 1; need &= need - 1;
                const uint32_t key = __shfl_sync(0xffffffffu, hk, l);
                uint32_t cc = (vme.x == key) + (vme.y == key) + (vme.z == key) + (vme.w == key);
                cc = __reduce_add_sync(0xffffffffu, cc);
                if (lane == l) cr_acc += (key == 0u) ? cc - pad : cc;
            }
        }

        if (t < LEVELS - 1 && valid) {
            uint32_t msg = 0;
            uint64_t r = rlo;
            while (r) { int b = __ffsll((long long)r) - 1; r &= r - 1; msg += smh2[p][b]; }
            r = rhi;
            while (r) { int b = __ffsll((long long)r) - 1; r &= r - 1; msg += smh2[p][64 + b]; }
            hreg = mixh(hreg * 0x9E3779B1u + msg);
        }
        // no trailing barrier: next publish writes the other buffers
    }

    // ---- final reductions ----
    unsigned se = __reduce_add_sync(0xffffffffu, se_acc);
    if (lane == 0 && se) atomicAdd(&s_selfe, (int)se);

    uint32_t cr = cr_acc;                      // already gated by fmbit
    cr += __shfl_down_sync(0xffffffffu, cr, 4, 8);
    cr += __shfl_down_sync(0xffffffffu, cr, 2, 8);
    cr += __shfl_down_sync(0xffffffffu, cr, 1, 8);
    if ((lane & 7) == 0) atomicAdd(&s_cross[tid >> 3], (int)cr);
    __syncthreads();

    if (tid < FNUM) {
        float denom = sqrtf((float)s_selfe * s_selff[tid]);
        float v = (float)s_cross[tid] / denom;
        if (!isfinite(v)) v = 0.f;
        out[u * FNUM + tid] = v;
    }
}

// ---------------- launch ----------------
extern "C" void kernel_launch(void* const* d_in, const int* in_sizes, int n_in,
                              void* d_out, int out_size) {
    const float* x  = (const float*)d_in[0];
    const int*   ei = (const int*)d_in[1];
    const float* A  = (const float*)d_in[3];
    const float* X  = (const float*)d_in[4];
    float* out = (float*)d_out;

    const int N  = in_sizes[0] / LAB;
    const int E2 = in_sizes[1] / 2;

    const int eblocks = (E2 + 255) / 256;
    k_build<<<eblocks + 1, 256>>>(ei, E2, A, X);
    k_main<<<N, 128>>>(x, out);
}